// round 9
// baseline (speedup 1.0000x reference)
#include <cuda_runtime.h>
#include <cuda_fp16.h>
#include <cstdint>

// ---------------- problem constants ----------------
#define TOKENS 512
#define OUT_F  8192
#define IN_F   4096

#define BM 64
#define BN 128
#define BK 64
#define NKT (IN_F / BK)   // 64 k-tiles
#define NTHREADS 256

// ---------------- smem layout (dynamic) ----------------
// LUT: 256 x 8B (byte -> 4 fp16 ternary values)
#define OFF_LUT     0
#define OFF_ALPHA   2048
#define OFF_BIAS    2560
#define OFF_TILE    3072
// per buffer: A 64x64 fp16 (8KB) | B 128x64 fp16 (16KB)
#define TILE_STRIDE 24576
#define SMEM_BYTES  (OFF_TILE + 2 * TILE_STRIDE)   // 52224

// SW128-style XOR swizzle on 128B rows
#define SWZ(o) ((uint32_t)(o) ^ ((((uint32_t)(o)) >> 3) & 0x70))

__device__ __forceinline__ uint32_t smem_u32(const void* p) {
    uint32_t a;
    asm("{ .reg .u64 t; cvta.to.shared.u64 t, %1; cvt.u32.u64 %0, t; }"
        : "=r"(a) : "l"(p));
    return a;
}

#define LDSM4(R, addr) \
    asm volatile("ldmatrix.sync.aligned.m8n8.x4.shared.b16 {%0,%1,%2,%3}, [%4];" \
        : "=r"((R)[0]), "=r"((R)[1]), "=r"((R)[2]), "=r"((R)[3]) : "r"(addr))

#define MMA16816(C, A, b0, b1) \
    asm volatile("mma.sync.aligned.m16n8k16.row.col.f32.f16.f16.f32 " \
        "{%0,%1,%2,%3},{%4,%5,%6,%7},{%8,%9},{%0,%1,%2,%3};" \
        : "+f"((C)[0]), "+f"((C)[1]), "+f"((C)[2]), "+f"((C)[3]) \
        : "r"((A)[0]), "r"((A)[1]), "r"((A)[2]), "r"((A)[3]), "r"(b0), "r"(b1))

__device__ __forceinline__ uint32_t code_fp16(int c) {
    // 2 -> +1.0 fp16, 0 -> -1.0 fp16, 1/3 -> 0
    return c == 2 ? 0x3C00u : (c == 0 ? 0xBC00u : 0u);
}

__device__ __forceinline__ uint32_t f16x2(float a, float b) {
    __half2 h = __floats2half2_rn(a, b);
    return *reinterpret_cast<uint32_t*>(&h);
}

__global__ void __launch_bounds__(NTHREADS, 3)
ternary_gemm_fp16(const float* __restrict__ x,
                  const int*   __restrict__ wp,
                  const float* __restrict__ alpha,
                  const float* __restrict__ bias,
                  float*       __restrict__ out) {
    extern __shared__ char smem[];
    const uint32_t sb = smem_u32(smem);
    const int tid = threadIdx.x;
    const int wid = tid >> 5;
    const int L   = tid & 31;

    const int n0 = blockIdx.x * BN;   // output-feature tile
    const int m0 = blockIdx.y * BM;   // token tile

    const int wm = (wid & 1) * 32;    // warp m offset (rows)
    const int wn = (wid >> 1) * 32;   // warp n offset (cols)

    // ---------------- prologue: LUT + alpha/bias ----------------
    {
        uint32_t w0 = code_fp16(tid & 3) | (code_fp16((tid >> 2) & 3) << 16);
        uint32_t w1 = code_fp16((tid >> 4) & 3) | (code_fp16((tid >> 6) & 3) << 16);
        *reinterpret_cast<uint2*>(smem + OFF_LUT + tid * 8) = make_uint2(w0, w1);
    }
    if (tid < BN) {
        reinterpret_cast<float*>(smem + OFF_ALPHA)[tid] = alpha[n0 + tid];
        reinterpret_cast<float*>(smem + OFF_BIAS)[tid]  = bias[n0 + tid];
    }
    __syncthreads();

    // ---------------- per-lane ldmatrix address constants ----------------
    // A: [m][k] rows of 128B (64 k fp16). x4 matrices:
    // (m0-7,k0-7),(m8-15,k0-7),(m0-7,k8-15),(m8-15,k8-15)
    const int mrow = ((L >> 3) & 1) * 8 + (L & 7);
    const uint32_t a_kx  = (uint32_t)(L >> 4) * 16;
    const uint32_t axor  = (uint32_t)(mrow & 7) << 4;
    const uint32_t a_row = (uint32_t)(wm + mrow) * 128;
    // B: [n][k] rows of 128B. x4: (n0-7,k0-7),(n0-7,k8-15),(n8-15,k0-7),(n8-15,k8-15)
    const int nrow = (L >> 4) * 8 + (L & 7);
    const uint32_t b_kx  = (uint32_t)((L >> 3) & 1) * 16;
    const uint32_t bxor  = (uint32_t)(nrow & 7) << 4;
    const uint32_t b_row = (uint32_t)(wn + nrow) * 128;

    const float4* x4g = reinterpret_cast<const float4*>(x);
    const int4*   w4g = reinterpret_cast<const int4*>(wp);
    const uint2*  lut = reinterpret_cast<const uint2*>(smem + OFF_LUT);

    // A staging geometry: 512 units of 16B (8 fp16 = 8 k); 2 units / thread
    const int am0 = (tid + 0 * NTHREADS) >> 3, aj0 = (tid + 0 * NTHREADS) & 7;
    const int am1 = (tid + 1 * NTHREADS) >> 3, aj1 = (tid + 1 * NTHREADS) & 7;
    // B staging: 512 int4 units (each int4 = 4 packed words = 16 k); 2 / thread
    // n = u>>2 (0..127), wq = u&3 (which int4 within the row's 64-k slice)
    const int bn0 = (tid + 0 * NTHREADS) >> 2, bq0 = (tid + 0 * NTHREADS) & 3;
    const int bn1 = (tid + 1 * NTHREADS) >> 2, bq1 = (tid + 1 * NTHREADS) & 3;

    float acc[2][4][4];
    #pragma unroll
    for (int i = 0; i < 2; i++)
        #pragma unroll
        for (int j = 0; j < 4; j++)
            #pragma unroll
            for (int q = 0; q < 4; q++) acc[i][j][q] = 0.0f;

    float4 xa[4];
    int4   wv[2];

    // ---- load tile 0 ----
    xa[0] = x4g[(uint32_t)(m0 + am0) * (IN_F / 4) + aj0 * 2 + 0];
    xa[1] = x4g[(uint32_t)(m0 + am0) * (IN_F / 4) + aj0 * 2 + 1];
    xa[2] = x4g[(uint32_t)(m0 + am1) * (IN_F / 4) + aj1 * 2 + 0];
    xa[3] = x4g[(uint32_t)(m0 + am1) * (IN_F / 4) + aj1 * 2 + 1];
    wv[0] = w4g[(uint32_t)(n0 + bn0) * (IN_F / 16) + bq0];
    wv[1] = w4g[(uint32_t)(n0 + bn1) * (IN_F / 16) + bq1];

    // ---- store tile 0 into buf 0 ----
    {
        const uint32_t ab = sb + OFF_TILE;
        const uint32_t bb = ab + 8192;
        uint32_t h0 = f16x2(xa[0].x, xa[0].y), h1 = f16x2(xa[0].z, xa[0].w);
        uint32_t h2 = f16x2(xa[1].x, xa[1].y), h3 = f16x2(xa[1].z, xa[1].w);
        asm volatile("st.shared.v4.b32 [%0], {%1,%2,%3,%4};"
            :: "r"(ab + SWZ((uint32_t)am0 * 128 + (uint32_t)aj0 * 16)),
               "r"(h0), "r"(h1), "r"(h2), "r"(h3));
        h0 = f16x2(xa[2].x, xa[2].y); h1 = f16x2(xa[2].z, xa[2].w);
        h2 = f16x2(xa[3].x, xa[3].y); h3 = f16x2(xa[3].z, xa[3].w);
        asm volatile("st.shared.v4.b32 [%0], {%1,%2,%3,%4};"
            :: "r"(ab + SWZ((uint32_t)am1 * 128 + (uint32_t)aj1 * 16)),
               "r"(h0), "r"(h1), "r"(h2), "r"(h3));

        #pragma unroll
        for (int i = 0; i < 2; i++) {
            const int bn_ = i ? bn1 : bn0;
            const int bq_ = i ? bq1 : bq0;
            uint2 e0 = lut[wv[i].x & 255], e1 = lut[wv[i].y & 255];
            uint2 e2 = lut[wv[i].z & 255], e3 = lut[wv[i].w & 255];
            uint32_t o0 = (uint32_t)bn_ * 128 + (uint32_t)bq_ * 32;
            asm volatile("st.shared.v4.b32 [%0], {%1,%2,%3,%4};"
                :: "r"(bb + SWZ(o0)), "r"(e0.x), "r"(e0.y), "r"(e1.x), "r"(e1.y));
            asm volatile("st.shared.v4.b32 [%0], {%1,%2,%3,%4};"
                :: "r"(bb + SWZ(o0 + 16)), "r"(e2.x), "r"(e2.y), "r"(e3.x), "r"(e3.y));
        }
    }
    __syncthreads();

    // ---------------- main K loop ----------------
    #pragma unroll 1
    for (int kt = 0; kt < NKT; kt++) {
        // issue next tile's global loads early (overlap with MMA)
        if (kt + 1 < NKT) {
            const int kq = (kt + 1) * 16;
            xa[0] = x4g[(uint32_t)(m0 + am0) * (IN_F / 4) + kq + aj0 * 2 + 0];
            xa[1] = x4g[(uint32_t)(m0 + am0) * (IN_F / 4) + kq + aj0 * 2 + 1];
            xa[2] = x4g[(uint32_t)(m0 + am1) * (IN_F / 4) + kq + aj1 * 2 + 0];
            xa[3] = x4g[(uint32_t)(m0 + am1) * (IN_F / 4) + kq + aj1 * 2 + 1];
            wv[0] = w4g[(uint32_t)(n0 + bn0) * (IN_F / 16) + (kt + 1) * 4 + bq0];
            wv[1] = w4g[(uint32_t)(n0 + bn1) * (IN_F / 16) + (kt + 1) * 4 + bq1];
        }

        // ---- MMA on current buffer ----
        {
            const uint32_t base = sb + OFF_TILE + (uint32_t)(kt & 1) * TILE_STRIDE;
            const uint32_t ahb = base + a_row;
            const uint32_t bbb = base + 8192 + b_row;
            #pragma unroll
            for (int ks = 0; ks < 4; ks++) {
                const uint32_t koffa = ((uint32_t)(ks * 32) + a_kx) ^ axor;
                const uint32_t koffb = ((uint32_t)(ks * 32) + b_kx) ^ bxor;
                uint32_t bf[8];
                LDSM4(bf,     bbb + koffb);          // n atoms 0,1
                LDSM4(bf + 4, bbb + 2048 + koffb);   // n atoms 2,3
                #pragma unroll
                for (int ma = 0; ma < 2; ma++) {
                    uint32_t af[4];
                    LDSM4(af, ahb + (uint32_t)ma * 2048 + koffa);
                    MMA16816(acc[ma][0], af, bf[0], bf[1]);
                    MMA16816(acc[ma][1], af, bf[2], bf[3]);
                    MMA16816(acc[ma][2], af, bf[4], bf[5]);
                    MMA16816(acc[ma][3], af, bf[6], bf[7]);
                }
            }
        }

        // ---- store next tile into other buffer ----
        if (kt + 1 < NKT) {
            const uint32_t ab = sb + OFF_TILE + (uint32_t)((kt + 1) & 1) * TILE_STRIDE;
            const uint32_t bb = ab + 8192;
            uint32_t h0 = f16x2(xa[0].x, xa[0].y), h1 = f16x2(xa[0].z, xa[0].w);
            uint32_t h2 = f16x2(xa[1].x, xa[1].y), h3 = f16x2(xa[1].z, xa[1].w);
            asm volatile("st.shared.v4.b32 [%0], {%1,%2,%3,%4};"
                :: "r"(ab + SWZ((uint32_t)am0 * 128 + (uint32_t)aj0 * 16)),
                   "r"(h0), "r"(h1), "r"(h2), "r"(h3));
            h0 = f16x2(xa[2].x, xa[2].y); h1 = f16x2(xa[2].z, xa[2].w);
            h2 = f16x2(xa[3].x, xa[3].y); h3 = f16x2(xa[3].z, xa[3].w);
            asm volatile("st.shared.v4.b32 [%0], {%1,%2,%3,%4};"
                :: "r"(ab + SWZ((uint32_t)am1 * 128 + (uint32_t)aj1 * 16)),
                   "r"(h0), "r"(h1), "r"(h2), "r"(h3));

            #pragma unroll
            for (int i = 0; i < 2; i++) {
                const int bn_ = i ? bn1 : bn0;
                const int bq_ = i ? bq1 : bq0;
                uint2 e0 = lut[wv[i].x & 255], e1 = lut[wv[i].y & 255];
                uint2 e2 = lut[wv[i].z & 255], e3 = lut[wv[i].w & 255];
                uint32_t o0 = (uint32_t)bn_ * 128 + (uint32_t)bq_ * 32;
                asm volatile("st.shared.v4.b32 [%0], {%1,%2,%3,%4};"
                    :: "r"(bb + SWZ(o0)), "r"(e0.x), "r"(e0.y), "r"(e1.x), "r"(e1.y));
                asm volatile("st.shared.v4.b32 [%0], {%1,%2,%3,%4};"
                    :: "r"(bb + SWZ(o0 + 16)), "r"(e2.x), "r"(e2.y), "r"(e3.x), "r"(e3.y));
            }
        }
        __syncthreads();
    }

    // ---------------- epilogue ----------------
    const float* alpS = reinterpret_cast<const float*>(smem + OFF_ALPHA);
    const float* biaS = reinterpret_cast<const float*>(smem + OFF_BIAS);
    const int r  = L >> 2;
    const int c2 = (L & 3) * 2;

    #pragma unroll
    for (int ma = 0; ma < 2; ma++) {
        #pragma unroll
        for (int na = 0; na < 4; na++) {
            int cl = wn + na * 8 + c2;
            float A0 = alpS[cl], A1 = alpS[cl + 1];
            float B0 = biaS[cl], B1 = biaS[cl + 1];
            int gm = m0 + wm + ma * 16 + r;
            float* p = out + (uint32_t)gm * OUT_F + n0 + cl;
            float2 v0 = make_float2(fmaf(acc[ma][na][0], A0, B0),
                                    fmaf(acc[ma][na][1], A1, B1));
            *reinterpret_cast<float2*>(p) = v0;
            float2 v1 = make_float2(fmaf(acc[ma][na][2], A0, B0),
                                    fmaf(acc[ma][na][3], A1, B1));
            *reinterpret_cast<float2*>(p + 8 * OUT_F) = v1;
        }
    }
}

extern "C" void kernel_launch(void* const* d_in, const int* in_sizes, int n_in,
                              void* d_out, int out_size) {
    const float* x     = (const float*)d_in[0];
    const int*   wp    = (const int*)d_in[1];
    const float* alpha = (const float*)d_in[2];
    const float* bias  = (const float*)d_in[3];
    float*       out   = (float*)d_out;

    static bool configured = false;
    if (!configured) {
        cudaFuncSetAttribute(ternary_gemm_fp16,
                             cudaFuncAttributeMaxDynamicSharedMemorySize, SMEM_BYTES);
        configured = true;
    }

    dim3 grid(OUT_F / BN, TOKENS / BM);   // (64, 8) = 512 CTAs
    ternary_gemm_fp16<<<grid, NTHREADS, SMEM_BYTES>>>(x, wp, alpha, bias, out);
}

// round 10
// speedup vs baseline: 2.1714x; 2.1714x over previous
#include <cuda_runtime.h>
#include <cuda_fp16.h>
#include <cstdint>

// ---------------- problem constants ----------------
#define TOKENS 512
#define OUT_F  8192
#define IN_F   4096

#define BM 128
#define BN 128
#define BK 64
#define NKT (IN_F / BK)   // 64 k-tiles
#define NTHREADS 256

// ---------------- persistent scratch (device globals; no runtime alloc) ----
__device__ static __half g_x16[TOKENS * IN_F];          // 4 MB
__device__ static __half g_w16[(size_t)OUT_F * IN_F];   // 64 MB

// ---------------- smem layout (dynamic) ----------------
#define OFF_ALPHA   0
#define OFF_BIAS    512
#define OFF_TILE    1024
// per buffer: A 128x64 fp16 (16KB) | B 128x64 fp16 (16KB)
#define TILE_STRIDE 32768
#define SMEM_BYTES  (OFF_TILE + 2 * TILE_STRIDE)   // 66560

// SW128-style XOR swizzle on 128B rows
#define SWZ(o) ((uint32_t)(o) ^ ((((uint32_t)(o)) >> 3) & 0x70))

__device__ __forceinline__ uint32_t smem_u32(const void* p) {
    uint32_t a;
    asm("{ .reg .u64 t; cvta.to.shared.u64 t, %1; cvt.u32.u64 %0, t; }"
        : "=r"(a) : "l"(p));
    return a;
}

#define LDSM4(R, addr) \
    asm volatile("ldmatrix.sync.aligned.m8n8.x4.shared.b16 {%0,%1,%2,%3}, [%4];" \
        : "=r"((R)[0]), "=r"((R)[1]), "=r"((R)[2]), "=r"((R)[3]) : "r"(addr))

#define MMA16816(C, A, b0, b1) \
    asm volatile("mma.sync.aligned.m16n8k16.row.col.f32.f16.f16.f32 " \
        "{%0,%1,%2,%3},{%4,%5,%6,%7},{%8,%9},{%0,%1,%2,%3};" \
        : "+f"((C)[0]), "+f"((C)[1]), "+f"((C)[2]), "+f"((C)[3]) \
        : "r"((A)[0]), "r"((A)[1]), "r"((A)[2]), "r"((A)[3]), "r"(b0), "r"(b1))

#define CP16(dst, src) \
    asm volatile("cp.async.cg.shared.global [%0], [%1], 16;" \
        :: "r"(dst), "l"(__cvta_generic_to_global(src)) : "memory")
#define CP_COMMIT() asm volatile("cp.async.commit_group;" ::: "memory")
#define CP_WAIT0()  asm volatile("cp.async.wait_group 0;" ::: "memory")

__device__ __forceinline__ uint32_t f16x2(float a, float b) {
    __half2 h = __floats2half2_rn(a, b);
    return *reinterpret_cast<uint32_t*>(&h);
}

// code -> fp16 bits: 0 -> 0xBC00 (-1), 1 -> 0, 2 -> 0x3C00 (+1), 3 -> 0
__device__ __forceinline__ uint2 dec_word(int word) {
    const uint64_t T = 0x00003C000000BC00ull;
    uint32_t h0 = (uint32_t)(T >> ((word & 3) << 4)) & 0xFFFFu;
    uint32_t h1 = (uint32_t)(T >> (((word >> 2) & 3) << 4)) & 0xFFFFu;
    uint32_t h2 = (uint32_t)(T >> (((word >> 4) & 3) << 4)) & 0xFFFFu;
    uint32_t h3 = (uint32_t)(T >> (((word >> 6) & 3) << 4)) & 0xFFFFu;
    return make_uint2(h0 | (h1 << 16), h2 | (h3 << 16));
}

// ---------------- pre-kernels ----------------
__global__ void conv_x_fp16(const float4* __restrict__ x4) {
    uint32_t u = blockIdx.x * 256 + threadIdx.x;   // 524288 threads
    float4 v = x4[u];
    uint2 h;
    h.x = f16x2(v.x, v.y);
    h.y = f16x2(v.z, v.w);
    reinterpret_cast<uint2*>(g_x16)[u] = h;
}

__global__ void decode_w_fp16(const int4* __restrict__ w4) {
    uint32_t u = blockIdx.x * 256 + threadIdx.x;   // 2097152 threads
    int4 w = w4[u];
    uint2 d0 = dec_word(w.x), d1 = dec_word(w.y);
    uint2 d2 = dec_word(w.z), d3 = dec_word(w.w);
    uint4* dst = reinterpret_cast<uint4*>(g_w16) + (size_t)u * 2;
    dst[0] = make_uint4(d0.x, d0.y, d1.x, d1.y);
    dst[1] = make_uint4(d2.x, d2.y, d3.x, d3.y);
}

// ---------------- main GEMM ----------------
__global__ void __launch_bounds__(NTHREADS, 2)
ternary_gemm_fp16(const float* __restrict__ alpha,
                  const float* __restrict__ bias,
                  float*       __restrict__ out) {
    extern __shared__ char smem[];
    const uint32_t sb = smem_u32(smem);
    const int tid = threadIdx.x;
    const int wid = tid >> 5;
    const int L   = tid & 31;

    const int n0 = blockIdx.x * BN;   // output-feature tile
    const int m0 = blockIdx.y * BM;   // token tile

    const int wm = (wid & 1) * 64;    // warp m offset
    const int wn = (wid >> 1) * 32;   // warp n offset

    // ---------------- prologue: alpha/bias ----------------
    if (tid < BN) {
        reinterpret_cast<float*>(smem + OFF_ALPHA)[tid] = alpha[n0 + tid];
        reinterpret_cast<float*>(smem + OFF_BIAS)[tid]  = bias[n0 + tid];
    }

    // ---------------- per-lane ldmatrix address constants ----------------
    // A: [m][k] rows of 128B. x4: (m0-7,k0-7),(m8-15,k0-7),(m0-7,k8-15),(m8-15,k8-15)
    const int mrow = ((L >> 3) & 1) * 8 + (L & 7);
    const uint32_t a_kx  = (uint32_t)(L >> 4) * 16;
    const uint32_t axor  = (uint32_t)(mrow & 7) << 4;
    const uint32_t a_row = (uint32_t)(wm + mrow) * 128;
    // B: [n][k] rows of 128B. x4: (n0-7,k0-7),(n0-7,k8-15),(n8-15,k0-7),(n8-15,k8-15)
    const int nrow = (L >> 4) * 8 + (L & 7);
    const uint32_t b_kx  = (uint32_t)((L >> 3) & 1) * 16;
    const uint32_t bxor  = (uint32_t)(nrow & 7) << 4;
    const uint32_t b_row = (uint32_t)(wn + nrow) * 128;

    const __half* gx = g_x16;
    const __half* gw = g_w16;

    // cp.async staging: 1024 chunks of 16B per tile side; 4 chunks/thread
    const int cm = tid >> 3;          // base row within the 128 (rows tid/8 + 32*i)
    const int cj = tid & 7;           // 16B chunk within 128B row

    float acc[4][4][4];
    #pragma unroll
    for (int i = 0; i < 4; i++)
        #pragma unroll
        for (int j = 0; j < 4; j++)
            #pragma unroll
            for (int q = 0; q < 4; q++) acc[i][j][q] = 0.0f;

    // ---- issue tile 0 ----
    {
        const uint32_t ab = sb + OFF_TILE;
        const uint32_t bb = ab + 16384;
        #pragma unroll
        for (int i = 0; i < 4; i++) {
            int m = cm + i * 32;
            uint32_t dst = ab + SWZ((uint32_t)m * 128 + (uint32_t)cj * 16);
            CP16(dst, gx + (size_t)(m0 + m) * IN_F + cj * 8);
        }
        #pragma unroll
        for (int i = 0; i < 4; i++) {
            int n = cm + i * 32;
            uint32_t dst = bb + SWZ((uint32_t)n * 128 + (uint32_t)cj * 16);
            CP16(dst, gw + (size_t)(n0 + n) * IN_F + cj * 8);
        }
        CP_COMMIT();
    }

    // ---------------- main K loop ----------------
    #pragma unroll 1
    for (int kt = 0; kt < NKT; kt++) {
        CP_WAIT0();
        __syncthreads();   // tile kt resident; everyone done reading buf (kt-1)&1

        // issue tile kt+1 into the other buffer (overlaps with MMA below)
        if (kt + 1 < NKT) {
            const uint32_t ab = sb + OFF_TILE + (uint32_t)((kt + 1) & 1) * TILE_STRIDE;
            const uint32_t bb = ab + 16384;
            const int kk = (kt + 1) * BK + cj * 8;
            #pragma unroll
            for (int i = 0; i < 4; i++) {
                int m = cm + i * 32;
                uint32_t dst = ab + SWZ((uint32_t)m * 128 + (uint32_t)cj * 16);
                CP16(dst, gx + (size_t)(m0 + m) * IN_F + kk);
            }
            #pragma unroll
            for (int i = 0; i < 4; i++) {
                int n = cm + i * 32;
                uint32_t dst = bb + SWZ((uint32_t)n * 128 + (uint32_t)cj * 16);
                CP16(dst, gw + (size_t)(n0 + n) * IN_F + kk);
            }
        }
        CP_COMMIT();

        // ---- MMA on current buffer ----
        const uint32_t base = sb + OFF_TILE + (uint32_t)(kt & 1) * TILE_STRIDE;
        const uint32_t ahb = base + a_row;
        const uint32_t bbb = base + 16384 + b_row;
        #pragma unroll
        for (int ks = 0; ks < 4; ks++) {
            const uint32_t koffa = ((uint32_t)(ks * 32) + a_kx) ^ axor;
            const uint32_t koffb = ((uint32_t)(ks * 32) + b_kx) ^ bxor;
            uint32_t bf[8];
            LDSM4(bf,     bbb + koffb);          // n atoms 0,1
            LDSM4(bf + 4, bbb + 2048 + koffb);   // n atoms 2,3
            #pragma unroll
            for (int ma = 0; ma < 4; ma++) {
                uint32_t af[4];
                LDSM4(af, ahb + (uint32_t)ma * 2048 + koffa);
                MMA16816(acc[ma][0], af, bf[0], bf[1]);
                MMA16816(acc[ma][1], af, bf[2], bf[3]);
                MMA16816(acc[ma][2], af, bf[4], bf[5]);
                MMA16816(acc[ma][3], af, bf[6], bf[7]);
            }
        }
    }

    // ---------------- epilogue ----------------
    const float* alpS = reinterpret_cast<const float*>(smem + OFF_ALPHA);
    const float* biaS = reinterpret_cast<const float*>(smem + OFF_BIAS);
    const int r  = L >> 2;
    const int c2 = (L & 3) * 2;

    #pragma unroll
    for (int ma = 0; ma < 4; ma++) {
        #pragma unroll
        for (int na = 0; na < 4; na++) {
            int cl = wn + na * 8 + c2;
            float A0 = alpS[cl], A1 = alpS[cl + 1];
            float B0 = biaS[cl], B1 = biaS[cl + 1];
            int gm = m0 + wm + ma * 16 + r;
            float* p = out + (uint32_t)gm * OUT_F + n0 + cl;
            float2 v0 = make_float2(fmaf(acc[ma][na][0], A0, B0),
                                    fmaf(acc[ma][na][1], A1, B1));
            *reinterpret_cast<float2*>(p) = v0;
            float2 v1 = make_float2(fmaf(acc[ma][na][2], A0, B0),
                                    fmaf(acc[ma][na][3], A1, B1));
            *reinterpret_cast<float2*>(p + 8 * OUT_F) = v1;
        }
    }
}

extern "C" void kernel_launch(void* const* d_in, const int* in_sizes, int n_in,
                              void* d_out, int out_size) {
    const float* x     = (const float*)d_in[0];
    const int*   wp    = (const int*)d_in[1];
    const float* alpha = (const float*)d_in[2];
    const float* bias  = (const float*)d_in[3];
    float*       out   = (float*)d_out;

    static bool configured = false;
    if (!configured) {
        cudaFuncSetAttribute(ternary_gemm_fp16,
                             cudaFuncAttributeMaxDynamicSharedMemorySize, SMEM_BYTES);
        configured = true;
    }

    // pre-kernels: x fp32->fp16 (4MB), W 2-bit->fp16 (64MB)
    conv_x_fp16<<<TOKENS * IN_F / 4 / 256, 256>>>(
        reinterpret_cast<const float4*>(x));
    decode_w_fp16<<<(size_t)OUT_F * IN_F / 16 / 256, 256>>>(
        reinterpret_cast<const int4*>(wp));

    dim3 grid(OUT_F / BN, TOKENS / BM);   // (64, 4) = 256 CTAs
    ternary_gemm_fp16<<<grid, NTHREADS, SMEM_BYTES>>>(alpha, bias, out);
}